// round 9
// baseline (speedup 1.0000x reference)
#include <cuda_runtime.h>
#include <cstdint>

// QuantumLayer collapses analytically to out[b] = cos(x[b,0] + weights[0]):
//  - RY(w)RY(x)|0> = RY(x+w)|0> (angles add; product state).
//  - Qubit 0 is only ever a CNOT control; Z_0 commutes with the chain.
//  - <Z_0> = cos(x[b,0] + w[0]).
//
// R7 finding: 1.4-1.56 TB/s regardless of MLP/occupancy/grid => not a
// warp-issue limit. This round swaps the fetch mechanism to TMA bulk copies
// (cp.async.bulk, hardware-pipelined, issued by one thread) through a
// 4-stage x 8KB smem ring per CTA to test whether the wall is the SIMT load
// path or the memory system itself.

#define N_STAGES   4
#define STAGE_B    8192           // 8KB = 256 rows of 32B
#define ROWS_CHUNK 256
#define N_CHUNKS   8              // 8 x 8KB = 64KB per CTA
#define ROWS_CTA   2048           // 128 CTAs x 2048 = 262144
#define N_CTAS     128

struct __align__(128) Smem {
    float    data[N_STAGES * STAGE_B / 4];   // 32KB
    uint64_t full[N_STAGES];
    uint64_t empty[N_STAGES];
};

__device__ __forceinline__ uint32_t s2u(const void* p) {
    uint32_t a;
    asm("{ .reg .u64 t; cvta.to.shared.u64 t, %1; cvt.u32.u64 %0, t; }"
        : "=r"(a) : "l"(p));
    return a;
}

__device__ __forceinline__ void mbar_wait(uint32_t mbar, uint32_t parity) {
    asm volatile(
        "{\n\t.reg .pred P;\n\t"
        "W_%=:\n\t"
        "mbarrier.try_wait.parity.acquire.cta.shared::cta.b64 P, [%0], %1, 0x989680;\n\t"
        "@P bra.uni D_%=;\n\t"
        "bra.uni W_%=;\n\t"
        "D_%=:\n\t}"
        :: "r"(mbar), "r"(parity) : "memory");
}

__global__ __launch_bounds__(256)
void quantum_layer_tma(const float* __restrict__ x,
                       const float* __restrict__ w,
                       float* __restrict__ out)
{
    __shared__ Smem sm;
    const int tid = threadIdx.x;
    const int bid = blockIdx.x;
    const float w0 = __ldg(w);

    const uint32_t data_u  = s2u(sm.data);
    const uint32_t full_u  = s2u(sm.full);
    const uint32_t empty_u = s2u(sm.empty);

    if (tid == 0) {
        #pragma unroll
        for (int s = 0; s < N_STAGES; ++s) {
            asm volatile("mbarrier.init.shared.b64 [%0], 1;"
                         :: "r"(full_u + s * 8) : "memory");
            asm volatile("mbarrier.init.shared.b64 [%0], 256;"
                         :: "r"(empty_u + s * 8) : "memory");
        }
        asm volatile("fence.proxy.async.shared::cta;" ::: "memory");
    }
    __syncthreads();

    const char* gsrc_base = (const char*)(x) + (size_t)bid * ROWS_CTA * 32;

    // Prime the ring: issue first N_STAGES chunks
    if (tid == 0) {
        #pragma unroll
        for (int c = 0; c < N_STAGES; ++c) {
            uint32_t mb = full_u + c * 8;
            asm volatile("mbarrier.arrive.expect_tx.shared.b64 _, [%0], %1;"
                         :: "r"(mb), "r"(STAGE_B) : "memory");
            asm volatile(
                "cp.async.bulk.shared::cta.global.mbarrier::complete_tx::bytes "
                "[%0], [%1], %2, [%3];"
                :: "r"(data_u + c * STAGE_B),
                   "l"(gsrc_base + (size_t)c * STAGE_B),
                   "r"(STAGE_B), "r"(mb) : "memory");
        }
    }

    const int out_base = bid * ROWS_CTA;

    #pragma unroll
    for (int c = 0; c < N_CHUNKS; ++c) {
        const int s = c & (N_STAGES - 1);
        mbar_wait(full_u + s * 8, (c >> 2) & 1);

        // row tid of this chunk: element 0 of 32B row = float offset tid*8
        float a = sm.data[s * (STAGE_B / 4) + tid * 8];
        out[out_base + c * ROWS_CHUNK + tid] = __cosf(a + w0);

        asm volatile("mbarrier.arrive.shared.b64 _, [%0];"
                     :: "r"(empty_u + s * 8) : "memory");

        // refill this stage with chunk c+4 once all consumers are done
        if (tid == 0 && c + N_STAGES < N_CHUNKS) {
            mbar_wait(empty_u + s * 8, 0);
            uint32_t mb = full_u + s * 8;
            asm volatile("mbarrier.arrive.expect_tx.shared.b64 _, [%0], %1;"
                         :: "r"(mb), "r"(STAGE_B) : "memory");
            asm volatile(
                "cp.async.bulk.shared::cta.global.mbarrier::complete_tx::bytes "
                "[%0], [%1], %2, [%3];"
                :: "r"(data_u + s * STAGE_B),
                   "l"(gsrc_base + (size_t)(c + N_STAGES) * STAGE_B),
                   "r"(STAGE_B), "r"(mb) : "memory");
        }
    }
}

// Generic fallback (correctness safety for unexpected B)
__global__ __launch_bounds__(256)
void quantum_layer_scalar(const float* __restrict__ x,
                          const float* __restrict__ w,
                          float* __restrict__ out, int B)
{
    const float w0 = __ldg(w);
    int b = blockIdx.x * blockDim.x + threadIdx.x;
    if (b < B) out[b] = __cosf(__ldg(x + (size_t)b * 8) + w0);
}

extern "C" void kernel_launch(void* const* d_in, const int* in_sizes, int n_in,
                              void* d_out, int out_size)
{
    const float* x = (const float*)d_in[0];   // [B, 8] float32
    const float* w = (const float*)d_in[1];   // [8]   float32
    float* out = (float*)d_out;               // [B]   float32
    int B = out_size;

    if (B == N_CTAS * ROWS_CTA) {
        quantum_layer_tma<<<N_CTAS, 256>>>(x, w, out);
    } else {
        quantum_layer_scalar<<<(B + 255) / 256, 256>>>(x, w, out, B);
    }
}